// round 2
// baseline (speedup 1.0000x reference)
#include <cuda_runtime.h>
#include <math.h>

// Problem constants
#define BB    2
#define NN    2048
#define IND   256
#define DIMV  256
#define HH    8
#define DHH   32
#define ROWS  (BB*NN)          // 4096
#define TEMP  0.17677669529663687f  // fp32(1/sqrt(32))

#define MSG_OFF   0
#define SCORE_OFF 1048576       // ROWS*DIMV
#define IDX_OFF   1179648       // SCORE_OFF + ROWS*4*8

// Scratch (static device memory; no allocations allowed)
__device__ float g_xn [ROWS*IND];
__device__ float g_q  [ROWS*DIMV];   // layout [b][h][s][d]
__device__ float g_k  [ROWS*DIMV];   // layout [b][h][s][d]
__device__ float g_v  [ROWS*DIMV];   // layout [b][h][s][d]
__device__ float g_msg[ROWS*DIMV];   // layout [row][dim]

typedef unsigned long long ull;

__device__ __forceinline__ ull fma2(ull a, ull b, ull c) {
    ull d; asm("fma.rn.f32x2 %0,%1,%2,%3;" : "=l"(d) : "l"(a), "l"(b), "l"(c)); return d;
}
__device__ __forceinline__ ull pack2(float x) {
    ull d; unsigned u = __float_as_uint(x);
    asm("mov.b64 %0,{%1,%1};" : "=l"(d) : "r"(u)); return d;
}
__device__ __forceinline__ void unpack2(ull a, float& lo, float& hi) {
    unsigned x, y; asm("mov.b64 {%0,%1},%2;" : "=r"(x), "=r"(y) : "l"(a));
    lo = __uint_as_float(x); hi = __uint_as_float(y);
}

// ---------------------------------------------------------------------------
// 1) LayerNorm: one block per row. Two-pass variance (matches jnp.var),
//    IEEE sqrt + IEEE divide (matches XLA ops; immune to fast-math flags).
// ---------------------------------------------------------------------------
__global__ void ln_kernel(const float* __restrict__ x,
                          const float* __restrict__ gam,
                          const float* __restrict__ bet) {
    __shared__ float red[8];
    int row = blockIdx.x, tid = threadIdx.x;
    int w = tid >> 5, ln = tid & 31;
    float v = x[row*IND + tid];

    // pass 1: mean
    float s = v;
#pragma unroll
    for (int o = 16; o > 0; o >>= 1) s += __shfl_xor_sync(0xffffffffu, s, o);
    if (ln == 0) red[w] = s;
    __syncthreads();
    float S = 0.f;
#pragma unroll
    for (int i = 0; i < 8; i++) S += red[i];
    float mu = S * (1.0f/IND);

    // pass 2: variance of centered values
    float d  = v - mu;
    float q  = d * d;
    __syncthreads();
#pragma unroll
    for (int o = 16; o > 0; o >>= 1) q += __shfl_xor_sync(0xffffffffu, q, o);
    if (ln == 0) red[w] = q;
    __syncthreads();
    float Q = 0.f;
#pragma unroll
    for (int i = 0; i < 8; i++) Q += red[i];
    float var = Q * (1.0f/IND);

    float denom = __fsqrt_rn(var + 1e-5f);         // IEEE sqrt
    float xh    = __fdiv_rn(d, denom);             // IEEE divide
    g_xn[row*IND + tid] = xh * gam[tid] + bet[tid];
}

// ---------------------------------------------------------------------------
// 2) QKV GEMM: out[r][j] = sum_k xn[r][k] * W[j][k];  M=4096, N=768, K=256
//    Sequential ascending-k single-accumulator FFMA (matches cuBLAS/Eigen).
// ---------------------------------------------------------------------------
__global__ void qkv_gemm(const float* __restrict__ W) {
    __shared__ float As[32][65];
    __shared__ float Bs[32][65];
    int tid = threadIdx.x;
    int r0 = blockIdx.y * 64, n0 = blockIdx.x * 64;
    int tx = tid & 15, ty = tid >> 4;
    float c[4][4];
#pragma unroll
    for (int i = 0; i < 4; i++)
#pragma unroll
        for (int j = 0; j < 4; j++) c[i][j] = 0.f;

    for (int k0 = 0; k0 < 256; k0 += 32) {
#pragma unroll
        for (int r = 0; r < 2; r++) {
            int f = tid + 256*r;
            int m = f >> 3, k4 = (f & 7) << 2;
            float4 a = *(const float4*)&g_xn[(r0+m)*256 + k0 + k4];
            As[k4+0][m]=a.x; As[k4+1][m]=a.y; As[k4+2][m]=a.z; As[k4+3][m]=a.w;
            float4 b = *(const float4*)&W[(n0+m)*256 + k0 + k4];
            Bs[k4+0][m]=b.x; Bs[k4+1][m]=b.y; Bs[k4+2][m]=b.z; Bs[k4+3][m]=b.w;
        }
        __syncthreads();
#pragma unroll
        for (int kk = 0; kk < 32; kk++) {
            float a0 = As[kk][ty*4+0], a1 = As[kk][ty*4+1],
                  a2 = As[kk][ty*4+2], a3 = As[kk][ty*4+3];
            float b0 = Bs[kk][tx*4+0], b1 = Bs[kk][tx*4+1],
                  b2 = Bs[kk][tx*4+2], b3 = Bs[kk][tx*4+3];
            c[0][0]=fmaf(a0,b0,c[0][0]); c[0][1]=fmaf(a0,b1,c[0][1]); c[0][2]=fmaf(a0,b2,c[0][2]); c[0][3]=fmaf(a0,b3,c[0][3]);
            c[1][0]=fmaf(a1,b0,c[1][0]); c[1][1]=fmaf(a1,b1,c[1][1]); c[1][2]=fmaf(a1,b2,c[1][2]); c[1][3]=fmaf(a1,b3,c[1][3]);
            c[2][0]=fmaf(a2,b0,c[2][0]); c[2][1]=fmaf(a2,b1,c[2][1]); c[2][2]=fmaf(a2,b2,c[2][2]); c[2][3]=fmaf(a2,b3,c[2][3]);
            c[3][0]=fmaf(a3,b0,c[3][0]); c[3][1]=fmaf(a3,b1,c[3][1]); c[3][2]=fmaf(a3,b2,c[3][2]); c[3][3]=fmaf(a3,b3,c[3][3]);
        }
        __syncthreads();
    }
#pragma unroll
    for (int i = 0; i < 4; i++)
#pragma unroll
        for (int j = 0; j < 4; j++) {
            int row = r0 + ty*4 + i, col = n0 + tx*4 + j;
            int which = col >> 8, h = (col >> 5) & 7, d = col & 31;
            int b = row >> 11, s = row & 2047;
            float* dst = (which == 0) ? g_q : ((which == 1) ? g_k : g_v);
            dst[(((b<<3)+h)*2048 + s)*32 + d] = c[i][j];
        }
}

// ---------------------------------------------------------------------------
// 3) Attention: one thread per (query, head). 256 blocks x 128 threads.
//    Score dot = STRICT sequential ascending-d fp32 FMA chain (correlates
//    rounding with the reference's dot reduction). Unmasked softmax
//    accumulation + top-4 tracking; subtract top-4 at the end.
// ---------------------------------------------------------------------------
__global__ void __launch_bounds__(128) attn_kernel(float* __restrict__ out) {
    __shared__ float4 Ks[128][8];
    __shared__ float4 Vs[128][8];

    int bid = blockIdx.x;                 // 0..255
    int qg  = bid & 15;
    int bh  = bid >> 4;                   // 0..15
    int b   = bh >> 3, h = bh & 7;
    int tid = threadIdx.x;
    int l   = qg*128 + tid;

    const float4* qrow = (const float4*)(g_q + ((size_t)bh*2048 + l)*32);
    float q[32];
#pragma unroll
    for (int c = 0; c < 8; c++) {
        float4 f = qrow[c];
        q[4*c]=f.x; q[4*c+1]=f.y; q[4*c+2]=f.z; q[4*c+3]=f.w;
    }

    ull acc2[16];
#pragma unroll
    for (int i = 0; i < 16; i++) acc2[i] = 0ull;

    float Z = 0.f;
    float t0 = -3.0e38f, t1 = -3.0e38f, t2 = -3.0e38f, t3 = -3.0e38f;
    int   i0 = 0, i1 = 0, i2 = 0, i3 = 0;

    const float4* kb = (const float4*)(g_k + (size_t)bh*65536);
    const float4* vb = (const float4*)(g_v + (size_t)bh*65536);

    for (int s0 = 0; s0 < 2048; s0 += 128) {
        __syncthreads();
        {
            int j = tid, sw = j & 7;
            const float4* kg = kb + (size_t)(s0 + j)*8;
            const float4* vg = vb + (size_t)(s0 + j)*8;
#pragma unroll
            for (int c = 0; c < 8; c++) Ks[j][c ^ sw] = kg[c];
#pragma unroll
            for (int c = 0; c < 8; c++) Vs[j][c ^ sw] = vg[c];
        }
        __syncthreads();

#pragma unroll 2
        for (int j = 0; j < 128; j++) {
            int sw = j & 7;
            // load K row into regs (broadcast LDS.128)
            float kr[32];
#pragma unroll
            for (int c = 0; c < 8; c++) {
                float4 f = Ks[j][c ^ sw];
                kr[4*c]=f.x; kr[4*c+1]=f.y; kr[4*c+2]=f.z; kr[4*c+3]=f.w;
            }
            // strict sequential ascending-d FMA chain (matches ref reduction)
            float sc = 0.f;
#pragma unroll
            for (int d = 0; d < 32; d++) sc = fmaf(q[d], kr[d], sc);
            sc = sc * TEMP;

            float e = __expf(sc);
            Z += e;
            ull ep = pack2(e);

            // acc += e * v (packed f32x2 over d-pairs; loose tolerance)
#pragma unroll
            for (int c = 0; c < 8; c++) {
                ulonglong2 vv = *(const ulonglong2*)&Vs[j][c ^ sw];
                acc2[2*c]   = fma2(ep, vv.x, acc2[2*c]);
                acc2[2*c+1] = fma2(ep, vv.y, acc2[2*c+1]);
            }

            // top-4 on logit (strict > keeps earlier index on ties)
            int s = s0 + j;
            if (sc > t3) {
                if (sc > t1) {
                    if (sc > t0) { t3=t2;i3=i2; t2=t1;i2=i1; t1=t0;i1=i0; t0=sc;i0=s; }
                    else         { t3=t2;i3=i2; t2=t1;i2=i1; t1=sc;i1=s; }
                } else {
                    if (sc > t2) { t3=t2;i3=i2; t2=sc;i2=s; }
                    else         { t3=sc;i3=s; }
                }
            }
        }
    }

    // ---- finalize: subtract top-4 contributions, normalize ----
    float m[32];
#pragma unroll
    for (int i = 0; i < 16; i++) unpack2(acc2[i], m[2*i], m[2*i+1]);

    float e0 = __expf(t0), e1 = __expf(t1), e2v = __expf(t2), e3 = __expf(t3);
    const float* v0 = g_v + ((size_t)bh*2048 + i0)*32;
    const float* v1 = g_v + ((size_t)bh*2048 + i1)*32;
    const float* v2 = g_v + ((size_t)bh*2048 + i2)*32;
    const float* v3 = g_v + ((size_t)bh*2048 + i3)*32;
#pragma unroll
    for (int d = 0; d < 32; d++)
        m[d] -= e0*v0[d] + e1*v1[d] + e2v*v2[d] + e3*v3[d];

    float rZ = 1.0f / Z;
#pragma unroll
    for (int d = 0; d < 32; d++) m[d] *= rZ;

    float* mo = g_msg + ((size_t)(b*2048 + l))*256 + h*32;
#pragma unroll
    for (int i = 0; i < 8; i++)
        ((float4*)mo)[i] = make_float4(m[4*i], m[4*i+1], m[4*i+2], m[4*i+3]);

    int rowi = b*2048 + l;
    float* so = out + SCORE_OFF + rowi*32 + h;   // [row][t][h], t stride 8
    so[0]  = e0*rZ;  so[8]  = e1*rZ;  so[16] = e2v*rZ; so[24] = e3*rZ;
    float* io = out + IDX_OFF + rowi*32 + h;
    io[0]  = (float)i0; io[8]  = (float)i1; io[16] = (float)i2; io[24] = (float)i3;
}

// ---------------------------------------------------------------------------
// 4) Proj GEMM + bias + residual: out = msg @ Wp^T + b_proj + v_flat
// ---------------------------------------------------------------------------
__global__ void proj_gemm(const float* __restrict__ Wp,
                          const float* __restrict__ bp,
                          float* __restrict__ out) {
    __shared__ float As[32][65];
    __shared__ float Bs[32][65];
    int tid = threadIdx.x;
    int r0 = blockIdx.y * 64, n0 = blockIdx.x * 64;
    int tx = tid & 15, ty = tid >> 4;
    float c[4][4];
#pragma unroll
    for (int i = 0; i < 4; i++)
#pragma unroll
        for (int j = 0; j < 4; j++) c[i][j] = 0.f;

    for (int k0 = 0; k0 < 256; k0 += 32) {
#pragma unroll
        for (int r = 0; r < 2; r++) {
            int f = tid + 256*r;
            int m = f >> 3, k4 = (f & 7) << 2;
            float4 a = *(const float4*)&g_msg[(r0+m)*256 + k0 + k4];
            As[k4+0][m]=a.x; As[k4+1][m]=a.y; As[k4+2][m]=a.z; As[k4+3][m]=a.w;
            float4 b = *(const float4*)&Wp[(n0+m)*256 + k0 + k4];
            Bs[k4+0][m]=b.x; Bs[k4+1][m]=b.y; Bs[k4+2][m]=b.z; Bs[k4+3][m]=b.w;
        }
        __syncthreads();
#pragma unroll
        for (int kk = 0; kk < 32; kk++) {
            float a0 = As[kk][ty*4+0], a1 = As[kk][ty*4+1],
                  a2 = As[kk][ty*4+2], a3 = As[kk][ty*4+3];
            float b0 = Bs[kk][tx*4+0], b1 = Bs[kk][tx*4+1],
                  b2 = Bs[kk][tx*4+2], b3 = Bs[kk][tx*4+3];
            c[0][0]=fmaf(a0,b0,c[0][0]); c[0][1]=fmaf(a0,b1,c[0][1]); c[0][2]=fmaf(a0,b2,c[0][2]); c[0][3]=fmaf(a0,b3,c[0][3]);
            c[1][0]=fmaf(a1,b0,c[1][0]); c[1][1]=fmaf(a1,b1,c[1][1]); c[1][2]=fmaf(a1,b2,c[1][2]); c[1][3]=fmaf(a1,b3,c[1][3]);
            c[2][0]=fmaf(a2,b0,c[2][0]); c[2][1]=fmaf(a2,b1,c[2][1]); c[2][2]=fmaf(a2,b2,c[2][2]); c[2][3]=fmaf(a2,b3,c[2][3]);
            c[3][0]=fmaf(a3,b0,c[3][0]); c[3][1]=fmaf(a3,b1,c[3][1]); c[3][2]=fmaf(a3,b2,c[3][2]); c[3][3]=fmaf(a3,b3,c[3][3]);
        }
        __syncthreads();
    }
#pragma unroll
    for (int i = 0; i < 4; i++)
#pragma unroll
        for (int j = 0; j < 4; j++) {
            int row = r0 + ty*4 + i, col = n0 + tx*4 + j;
            int b = row >> 11, l = row & 2047, h = col >> 5, d = col & 31;
            float val = c[i][j] + bp[col]
                      + g_v[(((b<<3)+h)*2048 + l)*32 + d];
            out[row*256 + col] = val;
        }
}

// ---------------------------------------------------------------------------
extern "C" void kernel_launch(void* const* d_in, const int* in_sizes, int n_in,
                              void* d_out, int out_size) {
    const float* points = (const float*)d_in[0];
    const float* gam    = (const float*)d_in[1];
    const float* bet    = (const float*)d_in[2];
    const float* wqkv   = (const float*)d_in[3];
    const float* wproj  = (const float*)d_in[4];
    const float* bproj  = (const float*)d_in[5];
    float* out = (float*)d_out;

    ln_kernel<<<ROWS, 256>>>(points, gam, bet);
    qkv_gemm <<<dim3(12, 64), 256>>>(wqkv);
    attn_kernel<<<256, 128>>>(out);
    proj_gemm<<<dim3(4, 64), 256>>>(wproj, bproj, out);
}

// round 3
// speedup vs baseline: 1.2936x; 1.2936x over previous
#include <cuda_runtime.h>
#include <math.h>

// Problem constants
#define BB    2
#define NN    2048
#define IND   256
#define DIMV  256
#define HH    8
#define DHH   32
#define ROWS  (BB*NN)          // 4096
#define TEMP  0.17677669529663687f  // fp32(1/sqrt(32))

#define MSG_OFF   0
#define SCORE_OFF 1048576       // ROWS*DIMV
#define IDX_OFF   1179648       // SCORE_OFF + ROWS*4*8

// Scratch (static device memory; no allocations allowed)
__device__ float g_xn [ROWS*IND];
__device__ float g_q  [ROWS*DIMV];   // layout [b][h][s][d]
__device__ float g_k  [ROWS*DIMV];   // layout [b][h][s][d]
__device__ float g_v  [ROWS*DIMV];   // layout [b][h][s][d]
__device__ float g_msg[ROWS*DIMV];   // layout [row][dim]

typedef unsigned long long ull;

__device__ __forceinline__ ull fma2(ull a, ull b, ull c) {
    ull d; asm("fma.rn.f32x2 %0,%1,%2,%3;" : "=l"(d) : "l"(a), "l"(b), "l"(c)); return d;
}
__device__ __forceinline__ ull pack2(float x) {
    ull d; unsigned u = __float_as_uint(x);
    asm("mov.b64 %0,{%1,%1};" : "=l"(d) : "r"(u)); return d;
}
__device__ __forceinline__ void unpack2(ull a, float& lo, float& hi) {
    unsigned x, y; asm("mov.b64 {%0,%1},%2;" : "=r"(x), "=r"(y) : "l"(a));
    lo = __uint_as_float(x); hi = __uint_as_float(y);
}

// ---------------------------------------------------------------------------
// 1) LayerNorm: one block per row. Two-pass variance (matches jnp.var),
//    IEEE sqrt + IEEE divide.
// ---------------------------------------------------------------------------
__global__ void ln_kernel(const float* __restrict__ x,
                          const float* __restrict__ gam,
                          const float* __restrict__ bet) {
    __shared__ float red[8];
    int row = blockIdx.x, tid = threadIdx.x;
    int w = tid >> 5, ln = tid & 31;
    float v = x[row*IND + tid];

    float s = v;
#pragma unroll
    for (int o = 16; o > 0; o >>= 1) s += __shfl_xor_sync(0xffffffffu, s, o);
    if (ln == 0) red[w] = s;
    __syncthreads();
    float S = 0.f;
#pragma unroll
    for (int i = 0; i < 8; i++) S += red[i];
    float mu = S * (1.0f/IND);

    float d  = v - mu;
    float q  = d * d;
    __syncthreads();
#pragma unroll
    for (int o = 16; o > 0; o >>= 1) q += __shfl_xor_sync(0xffffffffu, q, o);
    if (ln == 0) red[w] = q;
    __syncthreads();
    float Q = 0.f;
#pragma unroll
    for (int i = 0; i < 8; i++) Q += red[i];
    float var = Q * (1.0f/IND);

    float denom = __fsqrt_rn(var + 1e-5f);
    float xh    = __fdiv_rn(d, denom);
    g_xn[row*IND + tid] = xh * gam[tid] + bet[tid];
}

// ---------------------------------------------------------------------------
// 2) QKV GEMM: 64x128 tile, 256 threads, 4 rows x 4 col-pairs per thread,
//    FFMA2 over column pairs (per-output sequential ascending-k preserved).
// ---------------------------------------------------------------------------
__global__ void __launch_bounds__(256) qkv_gemm(const float* __restrict__ W) {
    __shared__ float As[32][68];     // [k][m], row 272B (16B aligned)
    __shared__ ull   Bs2[32][66];    // [k][col-pair], row 528B
    int tid = threadIdx.x;
    int r0 = blockIdx.y * 64, n0 = blockIdx.x * 128;
    int tx = tid & 15, ty = tid >> 4;
    float* Bf = (float*)Bs2;         // row stride 132 floats

    ull c2[4][4];
#pragma unroll
    for (int i = 0; i < 4; i++)
#pragma unroll
        for (int u = 0; u < 4; u++) c2[i][u] = 0ull;

    for (int k0 = 0; k0 < 256; k0 += 32) {
#pragma unroll
        for (int r = 0; r < 2; r++) {
            int f = tid + 256*r;            // 0..511
            int m = f >> 3, k4 = (f & 7) << 2;
            float4 a = *(const float4*)&g_xn[(r0+m)*256 + k0 + k4];
            As[k4+0][m]=a.x; As[k4+1][m]=a.y; As[k4+2][m]=a.z; As[k4+3][m]=a.w;
        }
#pragma unroll
        for (int r = 0; r < 4; r++) {
            int f = tid + 256*r;            // 0..1023
            int m = f >> 3, k4 = (f & 7) << 2;   // m = col 0..127
            float4 b = *(const float4*)&W[(n0+m)*256 + k0 + k4];
            Bf[(k4+0)*132+m]=b.x; Bf[(k4+1)*132+m]=b.y;
            Bf[(k4+2)*132+m]=b.z; Bf[(k4+3)*132+m]=b.w;
        }
        __syncthreads();
#pragma unroll
        for (int kk = 0; kk < 32; kk++) {
            float4 a = *(const float4*)&As[kk][ty*4];
            ull ap0 = pack2(a.x), ap1 = pack2(a.y), ap2 = pack2(a.z), ap3 = pack2(a.w);
#pragma unroll
            for (int u = 0; u < 4; u++) {
                ull b = Bs2[kk][tx + 16*u];
                c2[0][u] = fma2(ap0, b, c2[0][u]);
                c2[1][u] = fma2(ap1, b, c2[1][u]);
                c2[2][u] = fma2(ap2, b, c2[2][u]);
                c2[3][u] = fma2(ap3, b, c2[3][u]);
            }
        }
        __syncthreads();
    }
#pragma unroll
    for (int i = 0; i < 4; i++)
#pragma unroll
        for (int u = 0; u < 4; u++) {
            float lo, hi; unpack2(c2[i][u], lo, hi);
            int row = r0 + ty*4 + i;
            int col = n0 + 2*(tx + 16*u);
            int which = col >> 8, h = (col >> 5) & 7, d = col & 31;
            int b = row >> 11, s = row & 2047;
            float* dst = (which == 0) ? g_q : ((which == 1) ? g_k : g_v);
            float2* p = (float2*)&dst[(((b<<3)+h)*2048 + s)*32 + d];
            *p = make_float2(lo, hi);
        }
}

// ---------------------------------------------------------------------------
// 3) Attention: one thread per (query, head), 256 blocks x 128 threads.
//    Key-pair packed scores: fma.rn.f32x2 lanes = two keys; each lane is a
//    strict sequential ascending-d fp32 FMA chain (bit-identical to scalar).
// ---------------------------------------------------------------------------
__global__ void __launch_bounds__(128, 3) attn_kernel(float* __restrict__ out) {
    __shared__ ull    Kp[64][34];    // Kp[p][d] = {K[2p][d], K[2p+1][d]}
    __shared__ float4 Vs[128][8];    // xor-swizzled

    int bid = blockIdx.x;                 // 0..255
    int qg  = bid & 15;
    int bh  = bid >> 4;                   // 0..15
    int b   = bh >> 3, h = bh & 7;
    int tid = threadIdx.x;
    int l   = qg*128 + tid;

    // load q, pack each element into both f32x2 lanes
    ull qp[32];
    {
        const float4* qrow = (const float4*)(g_q + ((size_t)bh*2048 + l)*32);
#pragma unroll
        for (int c = 0; c < 8; c++) {
            float4 f = qrow[c];
            qp[4*c+0] = pack2(f.x); qp[4*c+1] = pack2(f.y);
            qp[4*c+2] = pack2(f.z); qp[4*c+3] = pack2(f.w);
        }
    }

    ull acc2[16];
#pragma unroll
    for (int i = 0; i < 16; i++) acc2[i] = 0ull;

    float Z = 0.f;
    float t0 = -3.0e38f, t1 = -3.0e38f, t2 = -3.0e38f, t3 = -3.0e38f;
    int   i0 = 0, i1 = 0, i2 = 0, i3 = 0;

    const float4* kb = (const float4*)(g_k + (size_t)bh*65536);
    const float4* vb = (const float4*)(g_v + (size_t)bh*65536);

    for (int s0 = 0; s0 < 2048; s0 += 128) {
        __syncthreads();
        {
            int j = tid;
            const float4* kg = kb + (size_t)(s0 + j)*8;
            int p = j >> 1, wsel = j & 1;
            unsigned* krow = (unsigned*)&Kp[p][0];
#pragma unroll
            for (int c = 0; c < 8; c++) {
                float4 f = kg[c];
                krow[2*(4*c+0)+wsel] = __float_as_uint(f.x);
                krow[2*(4*c+1)+wsel] = __float_as_uint(f.y);
                krow[2*(4*c+2)+wsel] = __float_as_uint(f.z);
                krow[2*(4*c+3)+wsel] = __float_as_uint(f.w);
            }
            int sw = j & 7;
            const float4* vg = vb + (size_t)(s0 + j)*8;
#pragma unroll
            for (int c = 0; c < 8; c++) Vs[j][c ^ sw] = vg[c];
        }
        __syncthreads();

#pragma unroll 2
        for (int p = 0; p < 64; p++) {
            // packed score chain: lane0 = key 2p, lane1 = key 2p+1,
            // each lane strict sequential ascending-d
            const ulonglong2* kr = (const ulonglong2*)&Kp[p][0];
            ull sc2 = 0ull;
#pragma unroll
            for (int u = 0; u < 16; u++) {
                ulonglong2 kk = kr[u];
                sc2 = fma2(qp[2*u],   kk.x, sc2);
                sc2 = fma2(qp[2*u+1], kk.y, sc2);
            }
            float sA, sB; unpack2(sc2, sA, sB);
            sA *= TEMP; sB *= TEMP;

            float eA = __expf(sA), eB = __expf(sB);
            Z += eA; Z += eB;
            ull eAp = pack2(eA), eBp = pack2(eB);

            int jA = 2*p, jB = 2*p + 1;
            int swA = jA & 7, swB = jB & 7;
#pragma unroll
            for (int c = 0; c < 8; c++) {
                ulonglong2 va = *(const ulonglong2*)&Vs[jA][c ^ swA];
                acc2[2*c]   = fma2(eAp, va.x, acc2[2*c]);
                acc2[2*c+1] = fma2(eAp, va.y, acc2[2*c+1]);
            }
#pragma unroll
            for (int c = 0; c < 8; c++) {
                ulonglong2 vv = *(const ulonglong2*)&Vs[jB][c ^ swB];
                acc2[2*c]   = fma2(eBp, vv.x, acc2[2*c]);
                acc2[2*c+1] = fma2(eBp, vv.y, acc2[2*c+1]);
            }

            // top-4: process A then B (ascending index; strict >)
            int s = s0 + jA;
            if (sA > t3) {
                if (sA > t1) {
                    if (sA > t0) { t3=t2;i3=i2; t2=t1;i2=i1; t1=t0;i1=i0; t0=sA;i0=s; }
                    else         { t3=t2;i3=i2; t2=t1;i2=i1; t1=sA;i1=s; }
                } else {
                    if (sA > t2) { t3=t2;i3=i2; t2=sA;i2=s; }
                    else         { t3=sA;i3=s; }
                }
            }
            s = s0 + jB;
            if (sB > t3) {
                if (sB > t1) {
                    if (sB > t0) { t3=t2;i3=i2; t2=t1;i2=i1; t1=t0;i1=i0; t0=sB;i0=s; }
                    else         { t3=t2;i3=i2; t2=t1;i2=i1; t1=sB;i1=s; }
                } else {
                    if (sB > t2) { t3=t2;i3=i2; t2=sB;i2=s; }
                    else         { t3=sB;i3=s; }
                }
            }
        }
    }

    // ---- finalize: subtract top-4 contributions, normalize ----
    float m[32];
#pragma unroll
    for (int i = 0; i < 16; i++) unpack2(acc2[i], m[2*i], m[2*i+1]);

    float e0 = __expf(t0), e1 = __expf(t1), e2v = __expf(t2), e3 = __expf(t3);
    const float* v0 = g_v + ((size_t)bh*2048 + i0)*32;
    const float* v1 = g_v + ((size_t)bh*2048 + i1)*32;
    const float* v2 = g_v + ((size_t)bh*2048 + i2)*32;
    const float* v3 = g_v + ((size_t)bh*2048 + i3)*32;
#pragma unroll
    for (int d = 0; d < 32; d++)
        m[d] -= e0*v0[d] + e1*v1[d] + e2v*v2[d] + e3*v3[d];

    float rZ = 1.0f / Z;
#pragma unroll
    for (int d = 0; d < 32; d++) m[d] *= rZ;

    float* mo = g_msg + ((size_t)(b*2048 + l))*256 + h*32;
#pragma unroll
    for (int i = 0; i < 8; i++)
        ((float4*)mo)[i] = make_float4(m[4*i], m[4*i+1], m[4*i+2], m[4*i+3]);

    int rowi = b*2048 + l;
    float* so = out + SCORE_OFF + rowi*32 + h;   // [row][t][h], t stride 8
    so[0]  = e0*rZ;  so[8]  = e1*rZ;  so[16] = e2v*rZ; so[24] = e3*rZ;
    float* io = out + IDX_OFF + rowi*32 + h;
    io[0]  = (float)i0; io[8]  = (float)i1; io[16] = (float)i2; io[24] = (float)i3;
}

// ---------------------------------------------------------------------------
// 4) Proj GEMM + bias + residual: 64x128 tile, FFMA2 col pairs.
// ---------------------------------------------------------------------------
__global__ void __launch_bounds__(256) proj_gemm(const float* __restrict__ Wp,
                                                 const float* __restrict__ bp,
                                                 float* __restrict__ out) {
    __shared__ float As[32][68];
    __shared__ ull   Bs2[32][66];
    int tid = threadIdx.x;
    int r0 = blockIdx.y * 64, n0 = blockIdx.x * 128;
    int tx = tid & 15, ty = tid >> 4;
    float* Bf = (float*)Bs2;

    ull c2[4][4];
#pragma unroll
    for (int i = 0; i < 4; i++)
#pragma unroll
        for (int u = 0; u < 4; u++) c2[i][u] = 0ull;

    for (int k0 = 0; k0 < 256; k0 += 32) {
#pragma unroll
        for (int r = 0; r < 2; r++) {
            int f = tid + 256*r;
            int m = f >> 3, k4 = (f & 7) << 2;
            float4 a = *(const float4*)&g_msg[(r0+m)*256 + k0 + k4];
            As[k4+0][m]=a.x; As[k4+1][m]=a.y; As[k4+2][m]=a.z; As[k4+3][m]=a.w;
        }
#pragma unroll
        for (int r = 0; r < 4; r++) {
            int f = tid + 256*r;
            int m = f >> 3, k4 = (f & 7) << 2;
            float4 b = *(const float4*)&Wp[(n0+m)*256 + k0 + k4];
            Bf[(k4+0)*132+m]=b.x; Bf[(k4+1)*132+m]=b.y;
            Bf[(k4+2)*132+m]=b.z; Bf[(k4+3)*132+m]=b.w;
        }
        __syncthreads();
#pragma unroll
        for (int kk = 0; kk < 32; kk++) {
            float4 a = *(const float4*)&As[kk][ty*4];
            ull ap0 = pack2(a.x), ap1 = pack2(a.y), ap2 = pack2(a.z), ap3 = pack2(a.w);
#pragma unroll
            for (int u = 0; u < 4; u++) {
                ull b = Bs2[kk][tx + 16*u];
                c2[0][u] = fma2(ap0, b, c2[0][u]);
                c2[1][u] = fma2(ap1, b, c2[1][u]);
                c2[2][u] = fma2(ap2, b, c2[2][u]);
                c2[3][u] = fma2(ap3, b, c2[3][u]);
            }
        }
        __syncthreads();
    }
#pragma unroll
    for (int i = 0; i < 4; i++)
#pragma unroll
        for (int u = 0; u < 4; u++) {
            float lo, hi; unpack2(c2[i][u], lo, hi);
            int row = r0 + ty*4 + i;
            int col = n0 + 2*(tx + 16*u);
            int b = row >> 11, l = row & 2047, h = col >> 5, d = col & 31;
            const float* vres = &g_v[(((b<<3)+h)*2048 + l)*32 + d];
            float2 o;
            o.x = lo + bp[col]   + vres[0];
            o.y = hi + bp[col+1] + vres[1];
            *(float2*)&out[row*256 + col] = o;
        }
}

// ---------------------------------------------------------------------------
extern "C" void kernel_launch(void* const* d_in, const int* in_sizes, int n_in,
                              void* d_out, int out_size) {
    const float* points = (const float*)d_in[0];
    const float* gam    = (const float*)d_in[1];
    const float* bet    = (const float*)d_in[2];
    const float* wqkv   = (const float*)d_in[3];
    const float* wproj  = (const float*)d_in[4];
    const float* bproj  = (const float*)d_in[5];
    float* out = (float*)d_out;

    ln_kernel<<<ROWS, 256>>>(points, gam, bet);
    qkv_gemm <<<dim3(6, 64), 256>>>(wqkv);
    attn_kernel<<<256, 128>>>(out);
    proj_gemm<<<dim3(2, 64), 256>>>(wproj, bproj, out);
}